// round 5
// baseline (speedup 1.0000x reference)
#include <cuda_runtime.h>

// MonteCarloPooling: per 2x2 block of x, Gumbel-max categorical sample using
// pre-drawn uniforms u; output = sampled index (0..3) as float.
//
// Equivalence chain:
//   argmax_k [ log(max(b_k,EPS)) - log(-log(clip(u_k))) ]
// = argmax_k [ max(b_k,EPS) / (-log(clip(u_k))) ]          (exp monotone)
// = cross-multiply champion compare (t_k > 0):
//     b_i/t_i > b_j/t_j  <=>  b_i*t_j > b_j*t_i
//
// R5: 8 outputs/thread -> 16 front-batched LDG.128 per thread. Evidence from
// R2/R3/R4: DRAM% tracks per-warp loads-in-flight, not occupancy. In-flight
// loads/SM: R2 = 40 warps x 8 = 320; here ~24 warps x 16 = 384.

#define MCP_EPS 1e-12f

// x: (32,64,224,224) fp32; u: (32,64,112,112,4) fp32; out: (32,64,112,112) fp32
static constexpr unsigned PW  = 112;      // pooled width
static constexpr unsigned PH  = 112;      // pooled height
static constexpr unsigned W   = 224;      // input width
static constexpr unsigned SPR = PW / 8;   // 14 8-output spans per pooled row

__device__ __forceinline__ float mcp_pick(float b0, float b1, float b2, float b3,
                                          float4 uu)
{
    // t_k = -log(max(u_k, EPS)) > 0 (accurate logf: argmax flip budget)
    float t0 = -logf(fmaxf(uu.x, MCP_EPS));
    float t1 = -logf(fmaxf(uu.y, MCP_EPS));
    float t2 = -logf(fmaxf(uu.z, MCP_EPS));
    float t3 = -logf(fmaxf(uu.w, MCP_EPS));

    b0 = fmaxf(b0, MCP_EPS);
    b1 = fmaxf(b1, MCP_EPS);
    b2 = fmaxf(b2, MCP_EPS);
    b3 = fmaxf(b3, MCP_EPS);

    // first-occurrence argmax of b_k/t_k (strict >, jnp.argmax semantics)
    float bb = b0, bt = t0;
    int   idx = 0;
    if (b1 * bt > bb * t1) { bb = b1; bt = t1; idx = 1; }
    if (b2 * bt > bb * t2) { bb = b2; bt = t2; idx = 2; }
    if (b3 * bt > bb * t3) { idx = 3; }
    return (float)idx;
}

__global__ void __launch_bounds__(256)
mcpool_kernel(const float* __restrict__ x,
              const float* __restrict__ u,
              float* __restrict__ out,
              unsigned n8)  // number of 8-output spans
{
    unsigned t = blockIdx.x * blockDim.x + threadIdx.x;
    if (t >= n8) return;

    // 32-bit decomposition, constant divisors -> magic multiplies
    unsigned s   = t % SPR;        // span within pooled row (0..13)
    unsigned row = t / SPR;        // bc*PH + h
    unsigned h   = row % PH;
    unsigned bc  = row / PH;       // fused batch*channel (0..2047)

    // ---- front-batch all 16 loads ----
    // x rows 2h and 2h+1, input cols [16s, 16s+16): 4 contiguous float4 each
    const float4* xr0 = (const float4*)(x + (bc * (2u * PH) + 2u * h) * W + 16u * s);
    const float4* xr1 = (const float4*)((const float*)xr0 + W);
    float4 a0 = __ldcs(xr0 + 0);
    float4 a1 = __ldcs(xr0 + 1);
    float4 a2 = __ldcs(xr0 + 2);
    float4 a3 = __ldcs(xr0 + 3);
    float4 c0 = __ldcs(xr1 + 0);
    float4 c1 = __ldcs(xr1 + 1);
    float4 c2 = __ldcs(xr1 + 2);
    float4 c3 = __ldcs(xr1 + 3);

    // u: 32 contiguous floats per span
    const float4* up = (const float4*)u + (t * 8u);
    float4 u0 = __ldcs(up + 0);
    float4 u1 = __ldcs(up + 1);
    float4 u2 = __ldcs(up + 2);
    float4 u3 = __ldcs(up + 3);
    float4 u4 = __ldcs(up + 4);
    float4 u5 = __ldcs(up + 5);
    float4 u6 = __ldcs(up + 6);
    float4 u7 = __ldcs(up + 7);

    // block flatten order k = 2*row_in_block + col_in_block
    float4 r0, r1;
    r0.x = mcp_pick(a0.x, a0.y, c0.x, c0.y, u0);
    r0.y = mcp_pick(a0.z, a0.w, c0.z, c0.w, u1);
    r0.z = mcp_pick(a1.x, a1.y, c1.x, c1.y, u2);
    r0.w = mcp_pick(a1.z, a1.w, c1.z, c1.w, u3);
    r1.x = mcp_pick(a2.x, a2.y, c2.x, c2.y, u4);
    r1.y = mcp_pick(a2.z, a2.w, c2.z, c2.w, u5);
    r1.z = mcp_pick(a3.x, a3.y, c3.x, c3.y, u6);
    r1.w = mcp_pick(a3.z, a3.w, c3.z, c3.w, u7);

    float4* op = (float4*)out + (t * 2u);
    __stcs(op + 0, r0);
    __stcs(op + 1, r1);
}

extern "C" void kernel_launch(void* const* d_in, const int* in_sizes, int n_in,
                              void* d_out, int out_size)
{
    const float* x = (const float*)d_in[0];
    const float* u = (const float*)d_in[1];
    float* out = (float*)d_out;

    unsigned n8 = (unsigned)(out_size / 8);   // 3,211,264 spans
    unsigned threads = 256;
    unsigned blocks = (n8 + threads - 1) / threads;
    mcpool_kernel<<<blocks, threads>>>(x, u, out, n8);
}

// round 6
// speedup vs baseline: 1.0325x; 1.0325x over previous
#include <cuda_runtime.h>

// MonteCarloPooling: per 2x2 block of x, Gumbel-max categorical sample using
// pre-drawn uniforms u; output = sampled index (0..3) as float.
//
// Equivalence chain:
//   argmax_k [ log(max(b_k,EPS)) - log(-log(clip(u_k))) ]
// = argmax_k [ max(b_k,EPS) / (-log(clip(u_k))) ]          (exp monotone)
// = cross-multiply champion compare (t_k > 0):
//     b_i/t_i > b_j/t_j  <=>  b_i*t_j > b_j*t_i
//
// R6: u-stream staged through smem via cp.async.cg (LDGSTS) — loads-in-flight
// decoupled from register pressure (R3/R4/R5 showed ptxas reg-minimization
// destroys register-resident load batches). x stays as 4x LDG.128.
// ubuf[4][256] layout: 16B lane stride -> conflict-free STS/LDS phases.
// No __syncthreads: each thread consumes only its own staged slots.

#define MCP_EPS 1e-12f

// x: (32,64,224,224) fp32; u: (32,64,112,112,4) fp32; out: (32,64,112,112) fp32
static constexpr unsigned PW  = 112;      // pooled width
static constexpr unsigned PH  = 112;      // pooled height
static constexpr unsigned W   = 224;      // input width
static constexpr unsigned GPR = PW / 4;   // 28 float4-groups per pooled row

__device__ __forceinline__ float mcp_pick(float b0, float b1, float b2, float b3,
                                          float4 uu)
{
    // t_k = -log(max(u_k, EPS)) > 0 (accurate logf: argmax-flip budget)
    float t0 = -logf(fmaxf(uu.x, MCP_EPS));
    float t1 = -logf(fmaxf(uu.y, MCP_EPS));
    float t2 = -logf(fmaxf(uu.z, MCP_EPS));
    float t3 = -logf(fmaxf(uu.w, MCP_EPS));

    b0 = fmaxf(b0, MCP_EPS);
    b1 = fmaxf(b1, MCP_EPS);
    b2 = fmaxf(b2, MCP_EPS);
    b3 = fmaxf(b3, MCP_EPS);

    // first-occurrence argmax of b_k/t_k (strict >, jnp.argmax semantics)
    float bb = b0, bt = t0;
    int   idx = 0;
    if (b1 * bt > bb * t1) { bb = b1; bt = t1; idx = 1; }
    if (b2 * bt > bb * t2) { bb = b2; bt = t2; idx = 2; }
    if (b3 * bt > bb * t3) { idx = 3; }
    return (float)idx;
}

__global__ void __launch_bounds__(256)
mcpool_kernel(const float* __restrict__ x,
              const float* __restrict__ u,
              float* __restrict__ out,
              unsigned n4)  // number of 4-output groups (multiple of 256 here)
{
    __shared__ float4 ubuf[4][256];   // 16 KB; [i][tid] -> conflict-free

    unsigned tid = threadIdx.x;
    unsigned t   = blockIdx.x * blockDim.x + tid;
    bool active  = (t < n4);

    // ---- stage u via cp.async.cg: 4 x 16B per thread, zero register cost ----
    if (active) {
        const float4* up = (const float4*)u + (t * 4u);
        unsigned s0 = (unsigned)__cvta_generic_to_shared(&ubuf[0][tid]);
        asm volatile("cp.async.cg.shared.global [%0], [%1], 16;\n"
                     :: "r"(s0),           "l"(up + 0) : "memory");
        asm volatile("cp.async.cg.shared.global [%0], [%1], 16;\n"
                     :: "r"(s0 + 4096u),   "l"(up + 1) : "memory");
        asm volatile("cp.async.cg.shared.global [%0], [%1], 16;\n"
                     :: "r"(s0 + 8192u),   "l"(up + 2) : "memory");
        asm volatile("cp.async.cg.shared.global [%0], [%1], 16;\n"
                     :: "r"(s0 + 12288u),  "l"(up + 3) : "memory");
    }
    asm volatile("cp.async.commit_group;\n" ::: "memory");

    if (!active) {
        asm volatile("cp.async.wait_group 0;\n" ::: "memory");
        return;
    }

    // 32-bit decomposition, constant divisors -> magic multiplies
    unsigned g   = t % GPR;        // float4-group within pooled row (0..27)
    unsigned row = t / GPR;        // bc*PH + h
    unsigned h   = row % PH;
    unsigned bc  = row / PH;       // fused batch*channel (0..2047)

    // ---- x loads: rows 2h and 2h+1, input cols [8g, 8g+8) ----
    const float* xbase = x + (bc * (2u * PH) + 2u * h) * W + 8u * g;
    float4 a0 = __ldcs((const float4*)xbase);           // top row, cols 8g..8g+3
    float4 a1 = __ldcs((const float4*)xbase + 1);       // top row, cols 8g+4..8g+7
    float4 c0 = __ldcs((const float4*)(xbase + W));     // bottom row
    float4 c1 = __ldcs((const float4*)(xbase + W) + 1);

    // wait for this thread's staged u (x LDGs already in flight)
    asm volatile("cp.async.wait_group 0;\n" ::: "memory");

    // block flatten order k = 2*row_in_block + col_in_block;
    // read each u vector just before use to keep live ranges short
    float4 res;
    res.x = mcp_pick(a0.x, a0.y, c0.x, c0.y, ubuf[0][tid]);
    res.y = mcp_pick(a0.z, a0.w, c0.z, c0.w, ubuf[1][tid]);
    res.z = mcp_pick(a1.x, a1.y, c1.x, c1.y, ubuf[2][tid]);
    res.w = mcp_pick(a1.z, a1.w, c1.z, c1.w, ubuf[3][tid]);

    __stcs((float4*)out + t, res);
}

extern "C" void kernel_launch(void* const* d_in, const int* in_sizes, int n_in,
                              void* d_out, int out_size)
{
    const float* x = (const float*)d_in[0];
    const float* u = (const float*)d_in[1];
    float* out = (float*)d_out;

    unsigned n4 = (unsigned)(out_size / 4);   // 6,422,528 groups (256 | n4)
    unsigned threads = 256;
    unsigned blocks = (n4 + threads - 1) / threads;
    mcpool_kernel<<<blocks, threads>>>(x, u, out, n4);
}

// round 7
// speedup vs baseline: 1.3397x; 1.2975x over previous
#include <cuda_runtime.h>

// MonteCarloPooling: per 2x2 block of x, Gumbel-max categorical sample using
// pre-drawn uniforms u; output = sampled index (0..3) as float.
//
// Equivalence chain:
//   argmax_k [ log(max(b_k,EPS)) - log(-log(clip(u_k))) ]
// = argmax_k [ max(b_k,EPS) / (-log(clip(u_k))) ]          (exp monotone)
// = cross-multiply champion compare (t_k > 0):
//     b_i/t_i > b_j/t_j  <=>  b_i*t_j > b_j*t_i
//
// R7: the 8x LDG.128 front batch is pinned with asm volatile so ptxas cannot
// narrow it (R3/R4/R5/R6 all showed dur tracks batched-loads-in-flight and
// every reg-pressure reduction let ptxas dismantle the batch). Epilogue uses
// the divide-free cross-multiply champion from R4.

#define MCP_EPS 1e-12f

// x: (32,64,224,224) fp32; u: (32,64,112,112,4) fp32; out: (32,64,112,112) fp32
static constexpr unsigned PW  = 112;      // pooled width
static constexpr unsigned PH  = 112;      // pooled height
static constexpr unsigned W   = 224;      // input width
static constexpr unsigned GPR = PW / 4;   // 28 float4-groups per pooled row

// ordering-pinned evict-streaming 128-bit load
__device__ __forceinline__ float4 ldcs_v4(const float4* p)
{
    float4 v;
    asm volatile("ld.global.cs.v4.f32 {%0,%1,%2,%3}, [%4];"
                 : "=f"(v.x), "=f"(v.y), "=f"(v.z), "=f"(v.w)
                 : "l"(p) : "memory");
    return v;
}

__device__ __forceinline__ float mcp_pick(float b0, float b1, float b2, float b3,
                                          float4 uu)
{
    // t_k = -log(max(u_k, EPS)) > 0 (accurate logf: argmax-flip budget ~10-90
    // flips at the 1e-3 threshold; MUFU.LG2's abs error near u->1 would
    // produce ~80+ flips -> too risky)
    float t0 = -logf(fmaxf(uu.x, MCP_EPS));
    float t1 = -logf(fmaxf(uu.y, MCP_EPS));
    float t2 = -logf(fmaxf(uu.z, MCP_EPS));
    float t3 = -logf(fmaxf(uu.w, MCP_EPS));

    b0 = fmaxf(b0, MCP_EPS);
    b1 = fmaxf(b1, MCP_EPS);
    b2 = fmaxf(b2, MCP_EPS);
    b3 = fmaxf(b3, MCP_EPS);

    // first-occurrence argmax of b_k/t_k (strict >, jnp.argmax semantics)
    float bb = b0, bt = t0;
    int   idx = 0;
    if (b1 * bt > bb * t1) { bb = b1; bt = t1; idx = 1; }
    if (b2 * bt > bb * t2) { bb = b2; bt = t2; idx = 2; }
    if (b3 * bt > bb * t3) { idx = 3; }
    return (float)idx;
}

__global__ void __launch_bounds__(256)
mcpool_kernel(const float* __restrict__ x,
              const float* __restrict__ u,
              float* __restrict__ out,
              unsigned n4)  // number of 4-output groups
{
    unsigned t = blockIdx.x * blockDim.x + threadIdx.x;
    if (t >= n4) return;

    // 32-bit decomposition, constant divisors -> magic multiplies
    unsigned g   = t % GPR;        // float4-group within pooled row (0..27)
    unsigned row = t / GPR;        // bc*PH + h
    unsigned h   = row % PH;
    unsigned bc  = row / PH;       // fused batch*channel (0..2047)

    // ---- pinned 8-wide front batch ----
    const float*  xbase = x + (bc * (2u * PH) + 2u * h) * W + 8u * g;
    const float4* xr0   = (const float4*)xbase;        // row 2h
    const float4* xr1   = (const float4*)(xbase + W);  // row 2h+1
    const float4* up    = (const float4*)u + (t * 4u);

    float4 a0 = ldcs_v4(xr0 + 0);   // top row, cols 8g..8g+3
    float4 a1 = ldcs_v4(xr0 + 1);   // top row, cols 8g+4..8g+7
    float4 c0 = ldcs_v4(xr1 + 0);   // bottom row
    float4 c1 = ldcs_v4(xr1 + 1);
    float4 u0 = ldcs_v4(up + 0);
    float4 u1 = ldcs_v4(up + 1);
    float4 u2 = ldcs_v4(up + 2);
    float4 u3 = ldcs_v4(up + 3);

    // block flatten order k = 2*row_in_block + col_in_block
    float4 res;
    res.x = mcp_pick(a0.x, a0.y, c0.x, c0.y, u0);
    res.y = mcp_pick(a0.z, a0.w, c0.z, c0.w, u1);
    res.z = mcp_pick(a1.x, a1.y, c1.x, c1.y, u2);
    res.w = mcp_pick(a1.z, a1.w, c1.z, c1.w, u3);

    __stcs((float4*)out + t, res);
}

extern "C" void kernel_launch(void* const* d_in, const int* in_sizes, int n_in,
                              void* d_out, int out_size)
{
    const float* x = (const float*)d_in[0];
    const float* u = (const float*)d_in[1];
    float* out = (float*)d_out;

    unsigned n4 = (unsigned)(out_size / 4);   // 6,422,528 groups
    unsigned threads = 256;
    unsigned blocks = (n4 + threads - 1) / threads;
    mcpool_kernel<<<blocks, threads>>>(x, u, out, n4);
}

// round 8
// speedup vs baseline: 1.3876x; 1.0357x over previous
#include <cuda_runtime.h>

// MonteCarloPooling: per 2x2 block of x, Gumbel-max categorical sample using
// pre-drawn uniforms u; output = sampled index (0..3) as float.
//
// Equivalence chain:
//   argmax_k [ log(max(b_k,EPS)) - log(-log(clip(u_k))) ]
// = argmax_k [ max(b_k,EPS) / (-log(clip(u_k))) ]          (exp monotone)
// = cross-multiply champion compare (t_k > 0):
//     b_i/t_i > b_j/t_j  <=>  b_i*t_j > b_j*t_i
//
// R8: kernel is issue/DRAM co-limited. Cheap epilogue (cross-multiply, R4)
// + __launch_bounds__(256, 5): reg cap 51 / occupancy target 5 CTAs = R2's
// envelope, so ptxas's latency scheduler keeps the 8x LDG.128 front batch
// (R4/R7 showed it collapses the batch only when chasing a 36-reg budget).

#define MCP_EPS 1e-12f

// x: (32,64,224,224) fp32; u: (32,64,112,112,4) fp32; out: (32,64,112,112) fp32
static constexpr unsigned PW  = 112;      // pooled width
static constexpr unsigned PH  = 112;      // pooled height
static constexpr unsigned W   = 224;      // input width
static constexpr unsigned GPR = PW / 4;   // 28 float4-groups per pooled row

__device__ __forceinline__ float mcp_pick(float b0, float b1, float b2, float b3,
                                          float4 uu)
{
    // t_k = -log(max(u_k, EPS)) > 0 (accurate logf: argmax-flip budget —
    // MUFU.LG2's absolute error near u->1 risks ~100x more flips)
    float t0 = -logf(fmaxf(uu.x, MCP_EPS));
    float t1 = -logf(fmaxf(uu.y, MCP_EPS));
    float t2 = -logf(fmaxf(uu.z, MCP_EPS));
    float t3 = -logf(fmaxf(uu.w, MCP_EPS));

    b0 = fmaxf(b0, MCP_EPS);
    b1 = fmaxf(b1, MCP_EPS);
    b2 = fmaxf(b2, MCP_EPS);
    b3 = fmaxf(b3, MCP_EPS);

    // first-occurrence argmax of b_k/t_k (strict >, jnp.argmax semantics)
    float bb = b0, bt = t0;
    int   idx = 0;
    if (b1 * bt > bb * t1) { bb = b1; bt = t1; idx = 1; }
    if (b2 * bt > bb * t2) { bb = b2; bt = t2; idx = 2; }
    if (b3 * bt > bb * t3) { idx = 3; }
    return (float)idx;
}

__global__ void __launch_bounds__(256, 5)
mcpool_kernel(const float* __restrict__ x,
              const float* __restrict__ u,
              float* __restrict__ out,
              unsigned n4)  // number of 4-output groups
{
    unsigned t = blockIdx.x * blockDim.x + threadIdx.x;
    if (t >= n4) return;

    // 32-bit decomposition, constant divisors -> magic multiplies
    unsigned g   = t % GPR;        // float4-group within pooled row (0..27)
    unsigned row = t / GPR;        // bc*PH + h
    unsigned h   = row % PH;
    unsigned bc  = row / PH;       // fused batch*channel (0..2047)

    // ---- 8-wide LDG.128 front batch ----
    const float*  xbase = x + (bc * (2u * PH) + 2u * h) * W + 8u * g;
    const float4* xr0   = (const float4*)xbase;        // row 2h
    const float4* xr1   = (const float4*)(xbase + W);  // row 2h+1
    const float4* up    = (const float4*)u + (t * 4u);

    float4 a0 = __ldcs(xr0 + 0);   // top row, cols 8g..8g+3
    float4 a1 = __ldcs(xr0 + 1);   // top row, cols 8g+4..8g+7
    float4 c0 = __ldcs(xr1 + 0);   // bottom row
    float4 c1 = __ldcs(xr1 + 1);
    float4 u0 = __ldcs(up + 0);
    float4 u1 = __ldcs(up + 1);
    float4 u2 = __ldcs(up + 2);
    float4 u3 = __ldcs(up + 3);

    // block flatten order k = 2*row_in_block + col_in_block
    float4 res;
    res.x = mcp_pick(a0.x, a0.y, c0.x, c0.y, u0);
    res.y = mcp_pick(a0.z, a0.w, c0.z, c0.w, u1);
    res.z = mcp_pick(a1.x, a1.y, c1.x, c1.y, u2);
    res.w = mcp_pick(a1.z, a1.w, c1.z, c1.w, u3);

    __stcs((float4*)out + t, res);
}

extern "C" void kernel_launch(void* const* d_in, const int* in_sizes, int n_in,
                              void* d_out, int out_size)
{
    const float* x = (const float*)d_in[0];
    const float* u = (const float*)d_in[1];
    float* out = (float*)d_out;

    unsigned n4 = (unsigned)(out_size / 4);   // 6,422,528 groups
    unsigned threads = 256;
    unsigned blocks = (n4 + threads - 1) / threads;
    mcpool_kernel<<<blocks, threads>>>(x, u, out, n4);
}